// round 10
// baseline (speedup 1.0000x reference)
#include <cuda_runtime.h>
#include <math.h>

// GATClassifier_22033182228597 — CSR-by-dst pipeline, fast scan + fast k_agg path.
#define N_NODES 25000
#define E_EDGES 400000
#define IN_DIM  128
#define H_HEADS 4
#define F_DIM   64
#define HF      256
#define NH      (N_NODES * H_HEADS)
#define NHF     (N_NODES * HF)                 // 6,400,000
#define NHIN    (N_NODES * H_HEADS * IN_DIM)   // 12,800,000
#define EHIN    ((size_t)E_EDGES * H_HEADS * IN_DIM) // 204,800,000
#define NEG_SLOPE 0.2f
#define CHUNK 64
#define SCAN_BLOCKS 25                          // 25*1024 >= 25000

// ---------------- device scratch ------------------------------------------
__device__ float g_feat_hf[NHF];      // [N, H*F]
__device__ float g_el[NH];            // [N, 4]
__device__ float g_er[NH];            // [N, 4]
__device__ float g_agg[NHIN];         // [N, H, IN]
__device__ int   g_cnt[N_NODES];      // per-dst degree
__device__ int   g_scan[N_NODES];     // block-local inclusive scan
__device__ int   g_bsum[SCAN_BLOCKS]; // per-block totals
__device__ int   g_off[N_NODES + 1];  // CSR offsets
__device__ int   g_pos[N_NODES];      // placement cursors
__device__ int   g_eidx[E_EDGES];     // sorted-by-dst -> original edge id
__device__ int   g_esrc[E_EDGES];     // sorted-by-dst -> src node

// ---------------- K0: zero histogram --------------------------------------
__global__ void k_zero() {
    int i = blockIdx.x * blockDim.x + threadIdx.x;
    if (i < N_NODES) g_cnt[i] = 0;
}

// ---------------- K1: histogram of dst ------------------------------------
__global__ void k_hist(const int* __restrict__ dst) {
    int e = blockIdx.x * blockDim.x + threadIdx.x;
    if (e < E_EDGES) atomicAdd(&g_cnt[dst[e]], 1);
}

// ---------------- K2a: block-level inclusive scan (coalesced) -------------
__global__ void k_scan1() {
    const int t = threadIdx.x, b = blockIdx.x;
    const int idx = b * 1024 + t;
    int v = (idx < N_NODES) ? g_cnt[idx] : 0;
    const int lane = t & 31, w = t >> 5;
    // warp inclusive scan
    int x = v;
#pragma unroll
    for (int o = 1; o < 32; o <<= 1) {
        int y = __shfl_up_sync(0xffffffffu, x, o);
        if (lane >= o) x += y;
    }
    __shared__ int ws[32];
    if (lane == 31) ws[w] = x;
    __syncthreads();
    if (w == 0) {
        int s = ws[lane];
#pragma unroll
        for (int o = 1; o < 32; o <<= 1) {
            int y = __shfl_up_sync(0xffffffffu, s, o);
            if (lane >= o) s += y;
        }
        ws[lane] = s;
    }
    __syncthreads();
    int incl = x + (w > 0 ? ws[w - 1] : 0);
    if (idx < N_NODES) g_scan[idx] = incl;
    if (t == 1023) g_bsum[b] = incl;   // block total (padding adds 0)
}

// ---------------- K2b: add block offsets, emit g_off / g_pos --------------
__global__ void k_scan2() {
    const int t = threadIdx.x, b = blockIdx.x;
    __shared__ int boff;
    if (t == 0) {
        int s = 0;
        for (int i = 0; i < b; i++) s += g_bsum[i];
        boff = s;
    }
    __syncthreads();
    const int idx = b * 1024 + t;
    if (idx < N_NODES) {
        int incl = g_scan[idx] + boff;
        g_off[idx + 1] = incl;
        g_pos[idx]     = incl - g_cnt[idx];   // exclusive prefix
    }
    if (idx == 0) g_off[0] = 0;
}

// ---------------- K3: place edges into CSR --------------------------------
__global__ void k_place(const int* __restrict__ src, const int* __restrict__ dst) {
    int e = blockIdx.x * blockDim.x + threadIdx.x;
    if (e >= E_EDGES) return;
    int p = atomicAdd(&g_pos[dst[e]], 1);
    g_eidx[p] = e;
    g_esrc[p] = src[e];
}

// ---------------- K4: feat_hf = feat @ W^T --------------------------------
__global__ void k_gemm(const float* __restrict__ feat, const float* __restrict__ W) {
    __shared__ float sW[32 * 260];
    __shared__ float sF[32 * 33];
    const int tid  = threadIdx.x;
    const int row0 = blockIdx.x * 32;
    const int c0   = (tid & 63) * 4;
    const int r0   = (tid >> 6) * 8;

    float acc[8][4];
#pragma unroll
    for (int r = 0; r < 8; r++)
#pragma unroll
        for (int c = 0; c < 4; c++) acc[r][c] = 0.f;

    for (int kc = 0; kc < IN_DIM; kc += 32) {
        for (int i = tid; i < 32 * 256; i += 256) {
            int c = i >> 5, kk = i & 31;
            sW[kk * 260 + c] = W[c * IN_DIM + kc + kk];
        }
        for (int i = tid; i < 32 * 32; i += 256) {
            int r = i >> 5, kk = i & 31;
            int row = row0 + r;
            sF[r * 33 + kk] = (row < N_NODES) ? feat[row * IN_DIM + kc + kk] : 0.f;
        }
        __syncthreads();
#pragma unroll
        for (int kk = 0; kk < 32; kk++) {
            float4 wv = *(const float4*)&sW[kk * 260 + c0];
#pragma unroll
            for (int r = 0; r < 8; r++) {
                float fv = sF[(r0 + r) * 33 + kk];
                acc[r][0] += fv * wv.x;
                acc[r][1] += fv * wv.y;
                acc[r][2] += fv * wv.z;
                acc[r][3] += fv * wv.w;
            }
        }
        __syncthreads();
    }
#pragma unroll
    for (int r = 0; r < 8; r++) {
        int row = row0 + r0 + r;
        if (row < N_NODES)
            *(float4*)&g_feat_hf[row * HF + c0] =
                make_float4(acc[r][0], acc[r][1], acc[r][2], acc[r][3]);
    }
}

// ---------------- K5: el/er -----------------------------------------------
__global__ void k_elr(const float* __restrict__ al, const float* __restrict__ ar) {
    int wid  = (blockIdx.x * blockDim.x + threadIdx.x) >> 5;
    int lane = threadIdx.x & 31;
    if (wid >= NH) return;
    int n = wid >> 2, h = wid & 3;
    const float2* fh  = (const float2*)&g_feat_hf[n * HF + h * F_DIM];
    const float2* al2 = (const float2*)&al[h * F_DIM];
    const float2* ar2 = (const float2*)&ar[h * F_DIM];
    float2 f = fh[lane], a = al2[lane], b = ar2[lane];
    float sl = f.x * a.x + f.y * a.y;
    float sr = f.x * b.x + f.y * b.y;
#pragma unroll
    for (int o = 16; o; o >>= 1) {
        sl += __shfl_down_sync(0xffffffffu, sl, o);
        sr += __shfl_down_sync(0xffffffffu, sr, o);
    }
    if (lane == 0) { g_el[wid] = sl; g_er[wid] = sr; }
}

__device__ __forceinline__ float lrelu(float x) {
    return (x > 0.f) ? x : NEG_SLOPE * x;
}

// ---------------- K6: fused softmax + aggregation, one block per dst ------
// Fast path (degree <= CHUNK, covers ~all nodes at mean degree 16):
//   stage logits once in smem; per-thread serial max/sum (no block reductions).
__global__ __launch_bounds__(256) void k_agg(const float* __restrict__ feat,
                                             float* __restrict__ out_rst) {
    const int d   = blockIdx.x;
    const int tid = threadIdx.x;
    const int beg = g_off[d], end = g_off[d + 1];
    const int deg = end - beg;

    __shared__ float4 s_e[CHUNK];     // staged leaky-relu logits per edge
    __shared__ float  s_w[CHUNK][4];  // softmax weights
    __shared__ int    s_src[CHUNK];
    __shared__ float  s_red[8][4];
    __shared__ float  s_max[4], s_inv[4];

    const float4 er4 = *(const float4*)&g_er[d * 4];

    const int h_r  = tid >> 6;        // head for rst position
    const int i_f  = tid & 127;       // feat column
    const int h_a1 = tid >> 7;        // 0/1
    const int h_a2 = 2 + (tid >> 7);  // 2/3

    float racc = 0.f, a1 = 0.f, a2 = 0.f;

    if (deg <= CHUNK) {
        // ---- stage src + logits once --------------------------------
        if (tid < deg) {
            int s = g_esrc[beg + tid];
            s_src[tid] = s;
            float4 el4 = *(const float4*)&g_el[s * 4];
            s_e[tid] = make_float4(lrelu(el4.x + er4.x), lrelu(el4.y + er4.y),
                                   lrelu(el4.z + er4.z), lrelu(el4.w + er4.w));
        }
        __syncthreads();
        // ---- per-thread serial max+sum from smem (broadcast reads) --
        float m0 = -INFINITY, m1 = -INFINITY, m2 = -INFINITY, m3 = -INFINITY;
        for (int j = 0; j < deg; j++) {
            float4 e = s_e[j];
            m0 = fmaxf(m0, e.x); m1 = fmaxf(m1, e.y);
            m2 = fmaxf(m2, e.z); m3 = fmaxf(m3, e.w);
        }
        float z0 = 0.f, z1 = 0.f, z2 = 0.f, z3 = 0.f;
        for (int j = 0; j < deg; j++) {
            float4 e = s_e[j];
            z0 += __expf(e.x - m0); z1 += __expf(e.y - m1);
            z2 += __expf(e.z - m2); z3 += __expf(e.w - m3);
        }
        const float iv0 = 1.f / z0, iv1 = 1.f / z1, iv2 = 1.f / z2, iv3 = 1.f / z3;
        if (tid < deg) {
            float4 e = s_e[tid];
            s_w[tid][0] = __expf(e.x - m0) * iv0;
            s_w[tid][1] = __expf(e.y - m1) * iv1;
            s_w[tid][2] = __expf(e.z - m2) * iv2;
            s_w[tid][3] = __expf(e.w - m3) * iv3;
        }
        __syncthreads();
        int j = 0;
        for (; j + 3 < deg; j += 4) {
            int s0 = s_src[j], s1 = s_src[j + 1], s2 = s_src[j + 2], s3 = s_src[j + 3];
            float g0 = __ldg(&g_feat_hf[(size_t)s0 * HF + tid]);
            float g1 = __ldg(&g_feat_hf[(size_t)s1 * HF + tid]);
            float g2 = __ldg(&g_feat_hf[(size_t)s2 * HF + tid]);
            float g3 = __ldg(&g_feat_hf[(size_t)s3 * HF + tid]);
            float f0 = __ldg(&feat[(size_t)s0 * IN_DIM + i_f]);
            float f1 = __ldg(&feat[(size_t)s1 * IN_DIM + i_f]);
            float f2 = __ldg(&feat[(size_t)s2 * IN_DIM + i_f]);
            float f3 = __ldg(&feat[(size_t)s3 * IN_DIM + i_f]);
            racc += s_w[j][h_r] * g0 + s_w[j + 1][h_r] * g1
                  + s_w[j + 2][h_r] * g2 + s_w[j + 3][h_r] * g3;
            a1   += s_w[j][h_a1] * f0 + s_w[j + 1][h_a1] * f1
                  + s_w[j + 2][h_a1] * f2 + s_w[j + 3][h_a1] * f3;
            a2   += s_w[j][h_a2] * f0 + s_w[j + 1][h_a2] * f1
                  + s_w[j + 2][h_a2] * f2 + s_w[j + 3][h_a2] * f3;
        }
        for (; j < deg; j++) {
            int s = s_src[j];
            racc += s_w[j][h_r] * __ldg(&g_feat_hf[(size_t)s * HF + tid]);
            float f = __ldg(&feat[(size_t)s * IN_DIM + i_f]);
            a1 += s_w[j][h_a1] * f;
            a2 += s_w[j][h_a2] * f;
        }
    } else {
        // ---- general path (rare, degree > 64): block reductions -----
        float m0 = -INFINITY, m1 = -INFINITY, m2 = -INFINITY, m3 = -INFINITY;
        for (int i = beg + tid; i < end; i += 256) {
            int s = g_esrc[i];
            float4 el4 = *(const float4*)&g_el[s * 4];
            m0 = fmaxf(m0, lrelu(el4.x + er4.x));
            m1 = fmaxf(m1, lrelu(el4.y + er4.y));
            m2 = fmaxf(m2, lrelu(el4.z + er4.z));
            m3 = fmaxf(m3, lrelu(el4.w + er4.w));
        }
#pragma unroll
        for (int o = 16; o; o >>= 1) {
            m0 = fmaxf(m0, __shfl_xor_sync(0xffffffffu, m0, o));
            m1 = fmaxf(m1, __shfl_xor_sync(0xffffffffu, m1, o));
            m2 = fmaxf(m2, __shfl_xor_sync(0xffffffffu, m2, o));
            m3 = fmaxf(m3, __shfl_xor_sync(0xffffffffu, m3, o));
        }
        if ((tid & 31) == 0) {
            int w = tid >> 5;
            s_red[w][0] = m0; s_red[w][1] = m1; s_red[w][2] = m2; s_red[w][3] = m3;
        }
        __syncthreads();
        if (tid < 4) {
            float m = s_red[0][tid];
#pragma unroll
            for (int w = 1; w < 8; w++) m = fmaxf(m, s_red[w][tid]);
            s_max[tid] = m;
        }
        __syncthreads();
        const float mx0 = s_max[0], mx1 = s_max[1], mx2 = s_max[2], mx3 = s_max[3];

        float z0 = 0.f, z1 = 0.f, z2 = 0.f, z3 = 0.f;
        for (int i = beg + tid; i < end; i += 256) {
            int s = g_esrc[i];
            float4 el4 = *(const float4*)&g_el[s * 4];
            z0 += __expf(lrelu(el4.x + er4.x) - mx0);
            z1 += __expf(lrelu(el4.y + er4.y) - mx1);
            z2 += __expf(lrelu(el4.z + er4.z) - mx2);
            z3 += __expf(lrelu(el4.w + er4.w) - mx3);
        }
#pragma unroll
        for (int o = 16; o; o >>= 1) {
            z0 += __shfl_xor_sync(0xffffffffu, z0, o);
            z1 += __shfl_xor_sync(0xffffffffu, z1, o);
            z2 += __shfl_xor_sync(0xffffffffu, z2, o);
            z3 += __shfl_xor_sync(0xffffffffu, z3, o);
        }
        if ((tid & 31) == 0) {
            int w = tid >> 5;
            s_red[w][0] = z0; s_red[w][1] = z1; s_red[w][2] = z2; s_red[w][3] = z3;
        }
        __syncthreads();
        if (tid < 4) {
            float z = s_red[0][tid];
#pragma unroll
            for (int w = 1; w < 8; w++) z += s_red[w][tid];
            s_inv[tid] = 1.f / z;
        }
        __syncthreads();
        const float iv0 = s_inv[0], iv1 = s_inv[1], iv2 = s_inv[2], iv3 = s_inv[3];

        for (int c = beg; c < end; c += CHUNK) {
            int m = min(CHUNK, end - c);
            if (tid < m) {
                int s = g_esrc[c + tid];
                s_src[tid] = s;
                float4 el4 = *(const float4*)&g_el[s * 4];
                s_w[tid][0] = __expf(lrelu(el4.x + er4.x) - mx0) * iv0;
                s_w[tid][1] = __expf(lrelu(el4.y + er4.y) - mx1) * iv1;
                s_w[tid][2] = __expf(lrelu(el4.z + er4.z) - mx2) * iv2;
                s_w[tid][3] = __expf(lrelu(el4.w + er4.w) - mx3) * iv3;
            }
            __syncthreads();
            for (int j = 0; j < m; j++) {
                int s = s_src[j];
                racc += s_w[j][h_r] * __ldg(&g_feat_hf[(size_t)s * HF + tid]);
                float f = __ldg(&feat[(size_t)s * IN_DIM + i_f]);
                a1 += s_w[j][h_a1] * f;
                a2 += s_w[j][h_a2] * f;
            }
            __syncthreads();
        }
    }

    out_rst[(size_t)d * HF + tid] = fmaxf(racc, 0.f);
    g_agg[(size_t)d * 512 + tid]       = a1;
    g_agg[(size_t)d * 512 + 256 + tid] = a2;
}

// ---------------- K7: out_edge = |agg[src]-agg[dst]|, block per dst -------
__global__ __launch_bounds__(256) void k_oe(float* __restrict__ out_edge) {
    const int d   = blockIdx.x;
    const int beg = g_off[d], end = g_off[d + 1];
    if (beg == end) return;
    const int tid = threadIdx.x;
    __shared__ float2 s_d[256];
    const float2* A = (const float2*)g_agg;
    s_d[tid] = A[(size_t)d * 256 + tid];
    __syncthreads();
    const float2 b = s_d[tid];

    int e_cur = g_eidx[beg];
    int s_cur = g_esrc[beg];
    float2 a_cur = A[(size_t)s_cur * 256 + tid];

    for (int i = beg; i < end; i++) {
        int e_nxt = 0, s_nxt = 0;
        float2 a_nxt = make_float2(0.f, 0.f);
        if (i + 1 < end) {
            e_nxt = g_eidx[i + 1];
            s_nxt = g_esrc[i + 1];
            a_nxt = A[(size_t)s_nxt * 256 + tid];   // issue before consuming a_cur
        }
        float2 r = make_float2(fabsf(a_cur.x - b.x), fabsf(a_cur.y - b.y));
        __stcs((float2*)out_edge + (size_t)e_cur * 256 + tid, r);
        e_cur = e_nxt; s_cur = s_nxt; a_cur = a_nxt;
    }
}

// ---------------- launch ---------------------------------------------------
extern "C" void kernel_launch(void* const* d_in, const int* in_sizes, int n_in,
                              void* d_out, int out_size) {
    (void)in_sizes; (void)n_in;
    const float* feat = (const float*)d_in[0];
    const float* W    = (const float*)d_in[1];
    const float* al   = (const float*)d_in[2];
    const float* ar   = (const float*)d_in[3];
    const int*   src  = (const int*)d_in[4];
    const int*   dst  = (const int*)d_in[5];
    float* out = (float*)d_out;

    bool   has_rst  = ((size_t)out_size > EHIN);
    float* out_edge = out + (has_rst ? NHF : 0);
    float* rst_dst  = out;

    k_zero<<<(N_NODES + 255) / 256, 256>>>();
    k_hist<<<(E_EDGES + 255) / 256, 256>>>(dst);
    k_gemm<<<(N_NODES + 31) / 32, 256>>>(feat, W);
    k_scan1<<<SCAN_BLOCKS, 1024>>>();
    k_scan2<<<SCAN_BLOCKS, 1024>>>();
    k_place<<<(E_EDGES + 255) / 256, 256>>>(src, dst);
    k_elr<<<(NH * 32 + 255) / 256, 256>>>(al, ar);
    k_agg<<<N_NODES, 256>>>(feat, rst_dst);
    k_oe<<<N_NODES, 256>>>(out_edge);
    (void)has_rst;
}

// round 13
// speedup vs baseline: 1.1947x; 1.1947x over previous
#include <cuda_runtime.h>
#include <math.h>

// GATClassifier_22033182228597 — CSR-by-dst pipeline, fast scan + warp0-softmax k_agg.
#define N_NODES 25000
#define E_EDGES 400000
#define IN_DIM  128
#define H_HEADS 4
#define F_DIM   64
#define HF      256
#define NH      (N_NODES * H_HEADS)
#define NHF     (N_NODES * HF)                 // 6,400,000
#define NHIN    (N_NODES * H_HEADS * IN_DIM)   // 12,800,000
#define EHIN    ((size_t)E_EDGES * H_HEADS * IN_DIM) // 204,800,000
#define NEG_SLOPE 0.2f
#define CHUNK 64
#define SCAN_BLOCKS 25                          // 25*1024 >= 25000

// ---------------- device scratch ------------------------------------------
__device__ float g_feat_hf[NHF];      // [N, H*F]
__device__ float g_el[NH];            // [N, 4]
__device__ float g_er[NH];            // [N, 4]
__device__ float g_agg[NHIN];         // [N, H, IN]
__device__ int   g_cnt[N_NODES];      // per-dst degree
__device__ int   g_scan[N_NODES];     // block-local inclusive scan
__device__ int   g_bsum[SCAN_BLOCKS]; // per-block totals
__device__ int   g_off[N_NODES + 1];  // CSR offsets
__device__ int   g_pos[N_NODES];      // placement cursors
__device__ int   g_eidx[E_EDGES];     // sorted-by-dst -> original edge id
__device__ int   g_esrc[E_EDGES];     // sorted-by-dst -> src node

// ---------------- K0: zero histogram --------------------------------------
__global__ void k_zero() {
    int i = blockIdx.x * blockDim.x + threadIdx.x;
    if (i < N_NODES) g_cnt[i] = 0;
}

// ---------------- K1: histogram of dst ------------------------------------
__global__ void k_hist(const int* __restrict__ dst) {
    int e = blockIdx.x * blockDim.x + threadIdx.x;
    if (e < E_EDGES) atomicAdd(&g_cnt[dst[e]], 1);
}

// ---------------- K2a: block-level inclusive scan (coalesced) -------------
__global__ void k_scan1() {
    const int t = threadIdx.x, b = blockIdx.x;
    const int idx = b * 1024 + t;
    int v = (idx < N_NODES) ? g_cnt[idx] : 0;
    const int lane = t & 31, w = t >> 5;
    int x = v;
#pragma unroll
    for (int o = 1; o < 32; o <<= 1) {
        int y = __shfl_up_sync(0xffffffffu, x, o);
        if (lane >= o) x += y;
    }
    __shared__ int ws[32];
    if (lane == 31) ws[w] = x;
    __syncthreads();
    if (w == 0) {
        int s = ws[lane];
#pragma unroll
        for (int o = 1; o < 32; o <<= 1) {
            int y = __shfl_up_sync(0xffffffffu, s, o);
            if (lane >= o) s += y;
        }
        ws[lane] = s;
    }
    __syncthreads();
    int incl = x + (w > 0 ? ws[w - 1] : 0);
    if (idx < N_NODES) g_scan[idx] = incl;
    if (t == 1023) g_bsum[b] = incl;
}

// ---------------- K2b: add block offsets, emit g_off / g_pos --------------
__global__ void k_scan2() {
    const int t = threadIdx.x, b = blockIdx.x;
    __shared__ int boff;
    if (t == 0) {
        int s = 0;
        for (int i = 0; i < b; i++) s += g_bsum[i];
        boff = s;
    }
    __syncthreads();
    const int idx = b * 1024 + t;
    if (idx < N_NODES) {
        int incl = g_scan[idx] + boff;
        g_off[idx + 1] = incl;
        g_pos[idx]     = incl - g_cnt[idx];
    }
    if (idx == 0) g_off[0] = 0;
}

// ---------------- K3: place edges into CSR --------------------------------
__global__ void k_place(const int* __restrict__ src, const int* __restrict__ dst) {
    int e = blockIdx.x * blockDim.x + threadIdx.x;
    if (e >= E_EDGES) return;
    int p = atomicAdd(&g_pos[dst[e]], 1);
    g_eidx[p] = e;
    g_esrc[p] = src[e];
}

// ---------------- K4: feat_hf = feat @ W^T --------------------------------
__global__ void k_gemm(const float* __restrict__ feat, const float* __restrict__ W) {
    __shared__ float sW[32 * 260];
    __shared__ float sF[32 * 33];
    const int tid  = threadIdx.x;
    const int row0 = blockIdx.x * 32;
    const int c0   = (tid & 63) * 4;
    const int r0   = (tid >> 6) * 8;

    float acc[8][4];
#pragma unroll
    for (int r = 0; r < 8; r++)
#pragma unroll
        for (int c = 0; c < 4; c++) acc[r][c] = 0.f;

    for (int kc = 0; kc < IN_DIM; kc += 32) {
        for (int i = tid; i < 32 * 256; i += 256) {
            int c = i >> 5, kk = i & 31;
            sW[kk * 260 + c] = W[c * IN_DIM + kc + kk];
        }
        for (int i = tid; i < 32 * 32; i += 256) {
            int r = i >> 5, kk = i & 31;
            int row = row0 + r;
            sF[r * 33 + kk] = (row < N_NODES) ? feat[row * IN_DIM + kc + kk] : 0.f;
        }
        __syncthreads();
#pragma unroll
        for (int kk = 0; kk < 32; kk++) {
            float4 wv = *(const float4*)&sW[kk * 260 + c0];
#pragma unroll
            for (int r = 0; r < 8; r++) {
                float fv = sF[(r0 + r) * 33 + kk];
                acc[r][0] += fv * wv.x;
                acc[r][1] += fv * wv.y;
                acc[r][2] += fv * wv.z;
                acc[r][3] += fv * wv.w;
            }
        }
        __syncthreads();
    }
#pragma unroll
    for (int r = 0; r < 8; r++) {
        int row = row0 + r0 + r;
        if (row < N_NODES)
            *(float4*)&g_feat_hf[row * HF + c0] =
                make_float4(acc[r][0], acc[r][1], acc[r][2], acc[r][3]);
    }
}

// ---------------- K5: el/er -----------------------------------------------
__global__ void k_elr(const float* __restrict__ al, const float* __restrict__ ar) {
    int wid  = (blockIdx.x * blockDim.x + threadIdx.x) >> 5;
    int lane = threadIdx.x & 31;
    if (wid >= NH) return;
    int n = wid >> 2, h = wid & 3;
    const float2* fh  = (const float2*)&g_feat_hf[n * HF + h * F_DIM];
    const float2* al2 = (const float2*)&al[h * F_DIM];
    const float2* ar2 = (const float2*)&ar[h * F_DIM];
    float2 f = fh[lane], a = al2[lane], b = ar2[lane];
    float sl = f.x * a.x + f.y * a.y;
    float sr = f.x * b.x + f.y * b.y;
#pragma unroll
    for (int o = 16; o; o >>= 1) {
        sl += __shfl_down_sync(0xffffffffu, sl, o);
        sr += __shfl_down_sync(0xffffffffu, sr, o);
    }
    if (lane == 0) { g_el[wid] = sl; g_er[wid] = sr; }
}

__device__ __forceinline__ float lrelu(float x) {
    return (x > 0.f) ? x : NEG_SLOPE * x;
}

// ---------------- K6: fused softmax + aggregation, one block per dst ------
// deg <= 64: stage logits in smem once; WARP 0 does the max/sum reductions
// (<=2 elems/lane + shuffle). No redundant per-thread exp recomputation.
__global__ __launch_bounds__(256) void k_agg(const float* __restrict__ feat,
                                             float* __restrict__ out_rst) {
    const int d   = blockIdx.x;
    const int tid = threadIdx.x;
    const int beg = g_off[d], end = g_off[d + 1];
    const int deg = end - beg;

    __shared__ float4 s_e[CHUNK];     // staged leaky-relu logits per edge
    __shared__ float  s_w[CHUNK][4];  // softmax weights
    __shared__ int    s_src[CHUNK];
    __shared__ float  s_red[8][4];
    __shared__ float  s_max[4], s_inv[4];

    const float4 er4 = *(const float4*)&g_er[d * 4];

    const int h_r  = tid >> 6;        // head for rst position
    const int i_f  = tid & 127;       // feat column
    const int h_a1 = tid >> 7;        // 0/1
    const int h_a2 = 2 + (tid >> 7);  // 2/3

    float racc = 0.f, a1 = 0.f, a2 = 0.f;

    if (deg <= CHUNK) {
        // ---- stage src + logits once --------------------------------
        if (tid < deg) {
            int s = g_esrc[beg + tid];
            s_src[tid] = s;
            float4 el4 = *(const float4*)&g_el[s * 4];
            s_e[tid] = make_float4(lrelu(el4.x + er4.x), lrelu(el4.y + er4.y),
                                   lrelu(el4.z + er4.z), lrelu(el4.w + er4.w));
        }
        __syncthreads();
        // ---- warp 0: per-head max + exp-sum via shuffle -------------
        if (tid < 32) {
            float m0 = -INFINITY, m1 = -INFINITY, m2 = -INFINITY, m3 = -INFINITY;
            for (int j = tid; j < deg; j += 32) {
                float4 e = s_e[j];
                m0 = fmaxf(m0, e.x); m1 = fmaxf(m1, e.y);
                m2 = fmaxf(m2, e.z); m3 = fmaxf(m3, e.w);
            }
#pragma unroll
            for (int o = 16; o; o >>= 1) {
                m0 = fmaxf(m0, __shfl_xor_sync(0xffffffffu, m0, o));
                m1 = fmaxf(m1, __shfl_xor_sync(0xffffffffu, m1, o));
                m2 = fmaxf(m2, __shfl_xor_sync(0xffffffffu, m2, o));
                m3 = fmaxf(m3, __shfl_xor_sync(0xffffffffu, m3, o));
            }
            float z0 = 0.f, z1 = 0.f, z2 = 0.f, z3 = 0.f;
            for (int j = tid; j < deg; j += 32) {
                float4 e = s_e[j];
                z0 += __expf(e.x - m0); z1 += __expf(e.y - m1);
                z2 += __expf(e.z - m2); z3 += __expf(e.w - m3);
            }
#pragma unroll
            for (int o = 16; o; o >>= 1) {
                z0 += __shfl_xor_sync(0xffffffffu, z0, o);
                z1 += __shfl_xor_sync(0xffffffffu, z1, o);
                z2 += __shfl_xor_sync(0xffffffffu, z2, o);
                z3 += __shfl_xor_sync(0xffffffffu, z3, o);
            }
            if (tid == 0) {
                s_max[0] = m0; s_max[1] = m1; s_max[2] = m2; s_max[3] = m3;
                s_inv[0] = 1.f / z0; s_inv[1] = 1.f / z1;
                s_inv[2] = 1.f / z2; s_inv[3] = 1.f / z3;
            }
        }
        __syncthreads();
        if (tid < deg) {
            float4 e = s_e[tid];
            s_w[tid][0] = __expf(e.x - s_max[0]) * s_inv[0];
            s_w[tid][1] = __expf(e.y - s_max[1]) * s_inv[1];
            s_w[tid][2] = __expf(e.z - s_max[2]) * s_inv[2];
            s_w[tid][3] = __expf(e.w - s_max[3]) * s_inv[3];
        }
        __syncthreads();
        int j = 0;
        for (; j + 3 < deg; j += 4) {
            int s0 = s_src[j], s1 = s_src[j + 1], s2 = s_src[j + 2], s3 = s_src[j + 3];
            float g0 = __ldg(&g_feat_hf[(size_t)s0 * HF + tid]);
            float g1 = __ldg(&g_feat_hf[(size_t)s1 * HF + tid]);
            float g2 = __ldg(&g_feat_hf[(size_t)s2 * HF + tid]);
            float g3 = __ldg(&g_feat_hf[(size_t)s3 * HF + tid]);
            float f0 = __ldg(&feat[(size_t)s0 * IN_DIM + i_f]);
            float f1 = __ldg(&feat[(size_t)s1 * IN_DIM + i_f]);
            float f2 = __ldg(&feat[(size_t)s2 * IN_DIM + i_f]);
            float f3 = __ldg(&feat[(size_t)s3 * IN_DIM + i_f]);
            racc += s_w[j][h_r] * g0 + s_w[j + 1][h_r] * g1
                  + s_w[j + 2][h_r] * g2 + s_w[j + 3][h_r] * g3;
            a1   += s_w[j][h_a1] * f0 + s_w[j + 1][h_a1] * f1
                  + s_w[j + 2][h_a1] * f2 + s_w[j + 3][h_a1] * f3;
            a2   += s_w[j][h_a2] * f0 + s_w[j + 1][h_a2] * f1
                  + s_w[j + 2][h_a2] * f2 + s_w[j + 3][h_a2] * f3;
        }
        for (; j < deg; j++) {
            int s = s_src[j];
            racc += s_w[j][h_r] * __ldg(&g_feat_hf[(size_t)s * HF + tid]);
            float f = __ldg(&feat[(size_t)s * IN_DIM + i_f]);
            a1 += s_w[j][h_a1] * f;
            a2 += s_w[j][h_a2] * f;
        }
    } else {
        // ---- general path (degree > 64): block reductions -----------
        float m0 = -INFINITY, m1 = -INFINITY, m2 = -INFINITY, m3 = -INFINITY;
        for (int i = beg + tid; i < end; i += 256) {
            int s = g_esrc[i];
            float4 el4 = *(const float4*)&g_el[s * 4];
            m0 = fmaxf(m0, lrelu(el4.x + er4.x));
            m1 = fmaxf(m1, lrelu(el4.y + er4.y));
            m2 = fmaxf(m2, lrelu(el4.z + er4.z));
            m3 = fmaxf(m3, lrelu(el4.w + er4.w));
        }
#pragma unroll
        for (int o = 16; o; o >>= 1) {
            m0 = fmaxf(m0, __shfl_xor_sync(0xffffffffu, m0, o));
            m1 = fmaxf(m1, __shfl_xor_sync(0xffffffffu, m1, o));
            m2 = fmaxf(m2, __shfl_xor_sync(0xffffffffu, m2, o));
            m3 = fmaxf(m3, __shfl_xor_sync(0xffffffffu, m3, o));
        }
        if ((tid & 31) == 0) {
            int w = tid >> 5;
            s_red[w][0] = m0; s_red[w][1] = m1; s_red[w][2] = m2; s_red[w][3] = m3;
        }
        __syncthreads();
        if (tid < 4) {
            float m = s_red[0][tid];
#pragma unroll
            for (int w = 1; w < 8; w++) m = fmaxf(m, s_red[w][tid]);
            s_max[tid] = m;
        }
        __syncthreads();
        const float mx0 = s_max[0], mx1 = s_max[1], mx2 = s_max[2], mx3 = s_max[3];

        float z0 = 0.f, z1 = 0.f, z2 = 0.f, z3 = 0.f;
        for (int i = beg + tid; i < end; i += 256) {
            int s = g_esrc[i];
            float4 el4 = *(const float4*)&g_el[s * 4];
            z0 += __expf(lrelu(el4.x + er4.x) - mx0);
            z1 += __expf(lrelu(el4.y + er4.y) - mx1);
            z2 += __expf(lrelu(el4.z + er4.z) - mx2);
            z3 += __expf(lrelu(el4.w + er4.w) - mx3);
        }
#pragma unroll
        for (int o = 16; o; o >>= 1) {
            z0 += __shfl_xor_sync(0xffffffffu, z0, o);
            z1 += __shfl_xor_sync(0xffffffffu, z1, o);
            z2 += __shfl_xor_sync(0xffffffffu, z2, o);
            z3 += __shfl_xor_sync(0xffffffffu, z3, o);
        }
        if ((tid & 31) == 0) {
            int w = tid >> 5;
            s_red[w][0] = z0; s_red[w][1] = z1; s_red[w][2] = z2; s_red[w][3] = z3;
        }
        __syncthreads();
        if (tid < 4) {
            float z = s_red[0][tid];
#pragma unroll
            for (int w = 1; w < 8; w++) z += s_red[w][tid];
            s_inv[tid] = 1.f / z;
        }
        __syncthreads();
        const float iv0 = s_inv[0], iv1 = s_inv[1], iv2 = s_inv[2], iv3 = s_inv[3];

        for (int c = beg; c < end; c += CHUNK) {
            int m = min(CHUNK, end - c);
            if (tid < m) {
                int s = g_esrc[c + tid];
                s_src[tid] = s;
                float4 el4 = *(const float4*)&g_el[s * 4];
                s_w[tid][0] = __expf(lrelu(el4.x + er4.x) - mx0) * iv0;
                s_w[tid][1] = __expf(lrelu(el4.y + er4.y) - mx1) * iv1;
                s_w[tid][2] = __expf(lrelu(el4.z + er4.z) - mx2) * iv2;
                s_w[tid][3] = __expf(lrelu(el4.w + er4.w) - mx3) * iv3;
            }
            __syncthreads();
            for (int j = 0; j < m; j++) {
                int s = s_src[j];
                racc += s_w[j][h_r] * __ldg(&g_feat_hf[(size_t)s * HF + tid]);
                float f = __ldg(&feat[(size_t)s * IN_DIM + i_f]);
                a1 += s_w[j][h_a1] * f;
                a2 += s_w[j][h_a2] * f;
            }
            __syncthreads();
        }
    }

    out_rst[(size_t)d * HF + tid] = fmaxf(racc, 0.f);
    g_agg[(size_t)d * 512 + tid]       = a1;
    g_agg[(size_t)d * 512 + 256 + tid] = a2;
}

// ---------------- K7: out_edge = |agg[src]-agg[dst]|, block per dst -------
__global__ __launch_bounds__(256) void k_oe(float* __restrict__ out_edge) {
    const int d   = blockIdx.x;
    const int beg = g_off[d], end = g_off[d + 1];
    if (beg == end) return;
    const int tid = threadIdx.x;
    __shared__ float2 s_d[256];
    const float2* A = (const float2*)g_agg;
    s_d[tid] = A[(size_t)d * 256 + tid];
    __syncthreads();
    const float2 b = s_d[tid];

    int e_cur = g_eidx[beg];
    int s_cur = g_esrc[beg];
    float2 a_cur = A[(size_t)s_cur * 256 + tid];

    for (int i = beg; i < end; i++) {
        int e_nxt = 0, s_nxt = 0;
        float2 a_nxt = make_float2(0.f, 0.f);
        if (i + 1 < end) {
            e_nxt = g_eidx[i + 1];
            s_nxt = g_esrc[i + 1];
            a_nxt = A[(size_t)s_nxt * 256 + tid];
        }
        float2 r = make_float2(fabsf(a_cur.x - b.x), fabsf(a_cur.y - b.y));
        __stcs((float2*)out_edge + (size_t)e_cur * 256 + tid, r);
        e_cur = e_nxt; s_cur = s_nxt; a_cur = a_nxt;
    }
}

// ---------------- launch ---------------------------------------------------
extern "C" void kernel_launch(void* const* d_in, const int* in_sizes, int n_in,
                              void* d_out, int out_size) {
    (void)in_sizes; (void)n_in;
    const float* feat = (const float*)d_in[0];
    const float* W    = (const float*)d_in[1];
    const float* al   = (const float*)d_in[2];
    const float* ar   = (const float*)d_in[3];
    const int*   src  = (const int*)d_in[4];
    const int*   dst  = (const int*)d_in[5];
    float* out = (float*)d_out;

    bool   has_rst  = ((size_t)out_size > EHIN);
    float* out_edge = out + (has_rst ? NHF : 0);
    float* rst_dst  = out;

    k_zero<<<(N_NODES + 255) / 256, 256>>>();
    k_hist<<<(E_EDGES + 255) / 256, 256>>>(dst);
    k_gemm<<<(N_NODES + 31) / 32, 256>>>(feat, W);
    k_scan1<<<SCAN_BLOCKS, 1024>>>();
    k_scan2<<<SCAN_BLOCKS, 1024>>>();
    k_place<<<(E_EDGES + 255) / 256, 256>>>(src, dst);
    k_elr<<<(NH * 32 + 255) / 256, 256>>>(al, ar);
    k_agg<<<N_NODES, 256>>>(feat, rst_dst);
    k_oe<<<N_NODES, 256>>>(out_edge);
    (void)has_rst;
}

// round 14
// speedup vs baseline: 1.2268x; 1.0269x over previous
#include <cuda_runtime.h>
#include <math.h>

// GATClassifier_22033182228597 — CSR-by-dst pipeline; fast scan, warp0-softmax
// k_agg, 2-edge/iter float4 k_oe.
#define N_NODES 25000
#define E_EDGES 400000
#define IN_DIM  128
#define H_HEADS 4
#define F_DIM   64
#define HF      256
#define NH      (N_NODES * H_HEADS)
#define NHF     (N_NODES * HF)                 // 6,400,000
#define NHIN    (N_NODES * H_HEADS * IN_DIM)   // 12,800,000
#define EHIN    ((size_t)E_EDGES * H_HEADS * IN_DIM) // 204,800,000
#define NEG_SLOPE 0.2f
#define CHUNK 64
#define SCAN_BLOCKS 25                          // 25*1024 >= 25000

// ---------------- device scratch ------------------------------------------
__device__ float g_feat_hf[NHF];      // [N, H*F]
__device__ float g_el[NH];            // [N, 4]
__device__ float g_er[NH];            // [N, 4]
__device__ float g_agg[NHIN];         // [N, H, IN]
__device__ int   g_cnt[N_NODES];      // per-dst degree
__device__ int   g_scan[N_NODES];     // block-local inclusive scan
__device__ int   g_bsum[SCAN_BLOCKS]; // per-block totals
__device__ int   g_off[N_NODES + 1];  // CSR offsets
__device__ int   g_pos[N_NODES];      // placement cursors
__device__ int   g_eidx[E_EDGES];     // sorted-by-dst -> original edge id
__device__ int   g_esrc[E_EDGES];     // sorted-by-dst -> src node

// ---------------- K0: zero histogram --------------------------------------
__global__ void k_zero() {
    int i = blockIdx.x * blockDim.x + threadIdx.x;
    if (i < N_NODES) g_cnt[i] = 0;
}

// ---------------- K1: histogram of dst ------------------------------------
__global__ void k_hist(const int* __restrict__ dst) {
    int e = blockIdx.x * blockDim.x + threadIdx.x;
    if (e < E_EDGES) atomicAdd(&g_cnt[dst[e]], 1);
}

// ---------------- K2a: block-level inclusive scan (coalesced) -------------
__global__ void k_scan1() {
    const int t = threadIdx.x, b = blockIdx.x;
    const int idx = b * 1024 + t;
    int v = (idx < N_NODES) ? g_cnt[idx] : 0;
    const int lane = t & 31, w = t >> 5;
    int x = v;
#pragma unroll
    for (int o = 1; o < 32; o <<= 1) {
        int y = __shfl_up_sync(0xffffffffu, x, o);
        if (lane >= o) x += y;
    }
    __shared__ int ws[32];
    if (lane == 31) ws[w] = x;
    __syncthreads();
    if (w == 0) {
        int s = ws[lane];
#pragma unroll
        for (int o = 1; o < 32; o <<= 1) {
            int y = __shfl_up_sync(0xffffffffu, s, o);
            if (lane >= o) s += y;
        }
        ws[lane] = s;
    }
    __syncthreads();
    int incl = x + (w > 0 ? ws[w - 1] : 0);
    if (idx < N_NODES) g_scan[idx] = incl;
    if (t == 1023) g_bsum[b] = incl;
}

// ---------------- K2b: add block offsets, emit g_off / g_pos --------------
__global__ void k_scan2() {
    const int t = threadIdx.x, b = blockIdx.x;
    __shared__ int boff;
    if (t == 0) {
        int s = 0;
        for (int i = 0; i < b; i++) s += g_bsum[i];
        boff = s;
    }
    __syncthreads();
    const int idx = b * 1024 + t;
    if (idx < N_NODES) {
        int incl = g_scan[idx] + boff;
        g_off[idx + 1] = incl;
        g_pos[idx]     = incl - g_cnt[idx];
    }
    if (idx == 0) g_off[0] = 0;
}

// ---------------- K3: place edges into CSR --------------------------------
__global__ void k_place(const int* __restrict__ src, const int* __restrict__ dst) {
    int e = blockIdx.x * blockDim.x + threadIdx.x;
    if (e >= E_EDGES) return;
    int p = atomicAdd(&g_pos[dst[e]], 1);
    g_eidx[p] = e;
    g_esrc[p] = src[e];
}

// ---------------- K4: feat_hf = feat @ W^T --------------------------------
__global__ void k_gemm(const float* __restrict__ feat, const float* __restrict__ W) {
    __shared__ float sW[32 * 260];
    __shared__ float sF[32 * 33];
    const int tid  = threadIdx.x;
    const int row0 = blockIdx.x * 32;
    const int c0   = (tid & 63) * 4;
    const int r0   = (tid >> 6) * 8;

    float acc[8][4];
#pragma unroll
    for (int r = 0; r < 8; r++)
#pragma unroll
        for (int c = 0; c < 4; c++) acc[r][c] = 0.f;

    for (int kc = 0; kc < IN_DIM; kc += 32) {
        for (int i = tid; i < 32 * 256; i += 256) {
            int c = i >> 5, kk = i & 31;
            sW[kk * 260 + c] = W[c * IN_DIM + kc + kk];
        }
        for (int i = tid; i < 32 * 32; i += 256) {
            int r = i >> 5, kk = i & 31;
            int row = row0 + r;
            sF[r * 33 + kk] = (row < N_NODES) ? feat[row * IN_DIM + kc + kk] : 0.f;
        }
        __syncthreads();
#pragma unroll
        for (int kk = 0; kk < 32; kk++) {
            float4 wv = *(const float4*)&sW[kk * 260 + c0];
#pragma unroll
            for (int r = 0; r < 8; r++) {
                float fv = sF[(r0 + r) * 33 + kk];
                acc[r][0] += fv * wv.x;
                acc[r][1] += fv * wv.y;
                acc[r][2] += fv * wv.z;
                acc[r][3] += fv * wv.w;
            }
        }
        __syncthreads();
    }
#pragma unroll
    for (int r = 0; r < 8; r++) {
        int row = row0 + r0 + r;
        if (row < N_NODES)
            *(float4*)&g_feat_hf[row * HF + c0] =
                make_float4(acc[r][0], acc[r][1], acc[r][2], acc[r][3]);
    }
}

// ---------------- K5: el/er -----------------------------------------------
__global__ void k_elr(const float* __restrict__ al, const float* __restrict__ ar) {
    int wid  = (blockIdx.x * blockDim.x + threadIdx.x) >> 5;
    int lane = threadIdx.x & 31;
    if (wid >= NH) return;
    int n = wid >> 2, h = wid & 3;
    const float2* fh  = (const float2*)&g_feat_hf[n * HF + h * F_DIM];
    const float2* al2 = (const float2*)&al[h * F_DIM];
    const float2* ar2 = (const float2*)&ar[h * F_DIM];
    float2 f = fh[lane], a = al2[lane], b = ar2[lane];
    float sl = f.x * a.x + f.y * a.y;
    float sr = f.x * b.x + f.y * b.y;
#pragma unroll
    for (int o = 16; o; o >>= 1) {
        sl += __shfl_down_sync(0xffffffffu, sl, o);
        sr += __shfl_down_sync(0xffffffffu, sr, o);
    }
    if (lane == 0) { g_el[wid] = sl; g_er[wid] = sr; }
}

__device__ __forceinline__ float lrelu(float x) {
    return (x > 0.f) ? x : NEG_SLOPE * x;
}

// ---------------- K6: fused softmax + aggregation, one block per dst ------
__global__ __launch_bounds__(256) void k_agg(const float* __restrict__ feat,
                                             float* __restrict__ out_rst) {
    const int d   = blockIdx.x;
    const int tid = threadIdx.x;
    const int beg = g_off[d], end = g_off[d + 1];
    const int deg = end - beg;

    __shared__ float4 s_e[CHUNK];     // staged leaky-relu logits per edge
    __shared__ float  s_w[CHUNK][4];  // softmax weights
    __shared__ int    s_src[CHUNK];
    __shared__ float  s_red[8][4];
    __shared__ float  s_max[4], s_inv[4];

    const float4 er4 = *(const float4*)&g_er[d * 4];

    const int h_r  = tid >> 6;        // head for rst position
    const int i_f  = tid & 127;       // feat column
    const int h_a1 = tid >> 7;        // 0/1
    const int h_a2 = 2 + (tid >> 7);  // 2/3

    float racc = 0.f, a1 = 0.f, a2 = 0.f;

    if (deg <= CHUNK) {
        if (tid < deg) {
            int s = g_esrc[beg + tid];
            s_src[tid] = s;
            float4 el4 = *(const float4*)&g_el[s * 4];
            s_e[tid] = make_float4(lrelu(el4.x + er4.x), lrelu(el4.y + er4.y),
                                   lrelu(el4.z + er4.z), lrelu(el4.w + er4.w));
        }
        __syncthreads();
        if (tid < 32) {
            float m0 = -INFINITY, m1 = -INFINITY, m2 = -INFINITY, m3 = -INFINITY;
            for (int j = tid; j < deg; j += 32) {
                float4 e = s_e[j];
                m0 = fmaxf(m0, e.x); m1 = fmaxf(m1, e.y);
                m2 = fmaxf(m2, e.z); m3 = fmaxf(m3, e.w);
            }
#pragma unroll
            for (int o = 16; o; o >>= 1) {
                m0 = fmaxf(m0, __shfl_xor_sync(0xffffffffu, m0, o));
                m1 = fmaxf(m1, __shfl_xor_sync(0xffffffffu, m1, o));
                m2 = fmaxf(m2, __shfl_xor_sync(0xffffffffu, m2, o));
                m3 = fmaxf(m3, __shfl_xor_sync(0xffffffffu, m3, o));
            }
            float z0 = 0.f, z1 = 0.f, z2 = 0.f, z3 = 0.f;
            for (int j = tid; j < deg; j += 32) {
                float4 e = s_e[j];
                z0 += __expf(e.x - m0); z1 += __expf(e.y - m1);
                z2 += __expf(e.z - m2); z3 += __expf(e.w - m3);
            }
#pragma unroll
            for (int o = 16; o; o >>= 1) {
                z0 += __shfl_xor_sync(0xffffffffu, z0, o);
                z1 += __shfl_xor_sync(0xffffffffu, z1, o);
                z2 += __shfl_xor_sync(0xffffffffu, z2, o);
                z3 += __shfl_xor_sync(0xffffffffu, z3, o);
            }
            if (tid == 0) {
                s_max[0] = m0; s_max[1] = m1; s_max[2] = m2; s_max[3] = m3;
                s_inv[0] = 1.f / z0; s_inv[1] = 1.f / z1;
                s_inv[2] = 1.f / z2; s_inv[3] = 1.f / z3;
            }
        }
        __syncthreads();
        if (tid < deg) {
            float4 e = s_e[tid];
            s_w[tid][0] = __expf(e.x - s_max[0]) * s_inv[0];
            s_w[tid][1] = __expf(e.y - s_max[1]) * s_inv[1];
            s_w[tid][2] = __expf(e.z - s_max[2]) * s_inv[2];
            s_w[tid][3] = __expf(e.w - s_max[3]) * s_inv[3];
        }
        __syncthreads();
        int j = 0;
        for (; j + 3 < deg; j += 4) {
            int s0 = s_src[j], s1 = s_src[j + 1], s2 = s_src[j + 2], s3 = s_src[j + 3];
            float g0 = __ldg(&g_feat_hf[(size_t)s0 * HF + tid]);
            float g1 = __ldg(&g_feat_hf[(size_t)s1 * HF + tid]);
            float g2 = __ldg(&g_feat_hf[(size_t)s2 * HF + tid]);
            float g3 = __ldg(&g_feat_hf[(size_t)s3 * HF + tid]);
            float f0 = __ldg(&feat[(size_t)s0 * IN_DIM + i_f]);
            float f1 = __ldg(&feat[(size_t)s1 * IN_DIM + i_f]);
            float f2 = __ldg(&feat[(size_t)s2 * IN_DIM + i_f]);
            float f3 = __ldg(&feat[(size_t)s3 * IN_DIM + i_f]);
            racc += s_w[j][h_r] * g0 + s_w[j + 1][h_r] * g1
                  + s_w[j + 2][h_r] * g2 + s_w[j + 3][h_r] * g3;
            a1   += s_w[j][h_a1] * f0 + s_w[j + 1][h_a1] * f1
                  + s_w[j + 2][h_a1] * f2 + s_w[j + 3][h_a1] * f3;
            a2   += s_w[j][h_a2] * f0 + s_w[j + 1][h_a2] * f1
                  + s_w[j + 2][h_a2] * f2 + s_w[j + 3][h_a2] * f3;
        }
        for (; j < deg; j++) {
            int s = s_src[j];
            racc += s_w[j][h_r] * __ldg(&g_feat_hf[(size_t)s * HF + tid]);
            float f = __ldg(&feat[(size_t)s * IN_DIM + i_f]);
            a1 += s_w[j][h_a1] * f;
            a2 += s_w[j][h_a2] * f;
        }
    } else {
        // ---- general path (degree > 64): block reductions -----------
        float m0 = -INFINITY, m1 = -INFINITY, m2 = -INFINITY, m3 = -INFINITY;
        for (int i = beg + tid; i < end; i += 256) {
            int s = g_esrc[i];
            float4 el4 = *(const float4*)&g_el[s * 4];
            m0 = fmaxf(m0, lrelu(el4.x + er4.x));
            m1 = fmaxf(m1, lrelu(el4.y + er4.y));
            m2 = fmaxf(m2, lrelu(el4.z + er4.z));
            m3 = fmaxf(m3, lrelu(el4.w + er4.w));
        }
#pragma unroll
        for (int o = 16; o; o >>= 1) {
            m0 = fmaxf(m0, __shfl_xor_sync(0xffffffffu, m0, o));
            m1 = fmaxf(m1, __shfl_xor_sync(0xffffffffu, m1, o));
            m2 = fmaxf(m2, __shfl_xor_sync(0xffffffffu, m2, o));
            m3 = fmaxf(m3, __shfl_xor_sync(0xffffffffu, m3, o));
        }
        if ((tid & 31) == 0) {
            int w = tid >> 5;
            s_red[w][0] = m0; s_red[w][1] = m1; s_red[w][2] = m2; s_red[w][3] = m3;
        }
        __syncthreads();
        if (tid < 4) {
            float m = s_red[0][tid];
#pragma unroll
            for (int w = 1; w < 8; w++) m = fmaxf(m, s_red[w][tid]);
            s_max[tid] = m;
        }
        __syncthreads();
        const float mx0 = s_max[0], mx1 = s_max[1], mx2 = s_max[2], mx3 = s_max[3];

        float z0 = 0.f, z1 = 0.f, z2 = 0.f, z3 = 0.f;
        for (int i = beg + tid; i < end; i += 256) {
            int s = g_esrc[i];
            float4 el4 = *(const float4*)&g_el[s * 4];
            z0 += __expf(lrelu(el4.x + er4.x) - mx0);
            z1 += __expf(lrelu(el4.y + er4.y) - mx1);
            z2 += __expf(lrelu(el4.z + er4.z) - mx2);
            z3 += __expf(lrelu(el4.w + er4.w) - mx3);
        }
#pragma unroll
        for (int o = 16; o; o >>= 1) {
            z0 += __shfl_xor_sync(0xffffffffu, z0, o);
            z1 += __shfl_xor_sync(0xffffffffu, z1, o);
            z2 += __shfl_xor_sync(0xffffffffu, z2, o);
            z3 += __shfl_xor_sync(0xffffffffu, z3, o);
        }
        if ((tid & 31) == 0) {
            int w = tid >> 5;
            s_red[w][0] = z0; s_red[w][1] = z1; s_red[w][2] = z2; s_red[w][3] = z3;
        }
        __syncthreads();
        if (tid < 4) {
            float z = s_red[0][tid];
#pragma unroll
            for (int w = 1; w < 8; w++) z += s_red[w][tid];
            s_inv[tid] = 1.f / z;
        }
        __syncthreads();
        const float iv0 = s_inv[0], iv1 = s_inv[1], iv2 = s_inv[2], iv3 = s_inv[3];

        for (int c = beg; c < end; c += CHUNK) {
            int m = min(CHUNK, end - c);
            if (tid < m) {
                int s = g_esrc[c + tid];
                s_src[tid] = s;
                float4 el4 = *(const float4*)&g_el[s * 4];
                s_w[tid][0] = __expf(lrelu(el4.x + er4.x) - mx0) * iv0;
                s_w[tid][1] = __expf(lrelu(el4.y + er4.y) - mx1) * iv1;
                s_w[tid][2] = __expf(lrelu(el4.z + er4.z) - mx2) * iv2;
                s_w[tid][3] = __expf(lrelu(el4.w + er4.w) - mx3) * iv3;
            }
            __syncthreads();
            for (int j = 0; j < m; j++) {
                int s = s_src[j];
                racc += s_w[j][h_r] * __ldg(&g_feat_hf[(size_t)s * HF + tid]);
                float f = __ldg(&feat[(size_t)s * IN_DIM + i_f]);
                a1 += s_w[j][h_a1] * f;
                a2 += s_w[j][h_a2] * f;
            }
            __syncthreads();
        }
    }

    out_rst[(size_t)d * HF + tid] = fmaxf(racc, 0.f);
    g_agg[(size_t)d * 512 + tid]       = a1;
    g_agg[(size_t)d * 512 + 256 + tid] = a2;
}

// ---------------- K7: out_edge = |agg[src]-agg[dst]| -----------------------
// Block per dst; TWO edges per iteration (half-block each, float4 lanes).
__global__ __launch_bounds__(256) void k_oe(float* __restrict__ out_edge) {
    const int d   = blockIdx.x;
    const int beg = g_off[d], end = g_off[d + 1];
    if (beg == end) return;
    const int tid     = threadIdx.x;
    const int half    = tid >> 7;     // 0: edge i, 1: edge i+1
    const int lane128 = tid & 127;    // float4 position within row (128*16B = 2KB)

    __shared__ float4 s_d[128];
    const float4* A = (const float4*)g_agg;   // 128 float4 per (node,row)
    if (tid < 128) s_d[tid] = A[(size_t)d * 128 + tid];
    __syncthreads();
    const float4 b = s_d[lane128];

    for (int i = beg + half; i < end; i += 2) {
        int e = g_eidx[i];
        int s = g_esrc[i];
        float4 a = A[(size_t)s * 128 + lane128];
        float4 r = make_float4(fabsf(a.x - b.x), fabsf(a.y - b.y),
                               fabsf(a.z - b.z), fabsf(a.w - b.w));
        __stcs((float4*)out_edge + (size_t)e * 128 + lane128, r);
    }
}

// ---------------- launch ---------------------------------------------------
extern "C" void kernel_launch(void* const* d_in, const int* in_sizes, int n_in,
                              void* d_out, int out_size) {
    (void)in_sizes; (void)n_in;
    const float* feat = (const float*)d_in[0];
    const float* W    = (const float*)d_in[1];
    const float* al   = (const float*)d_in[2];
    const float* ar   = (const float*)d_in[3];
    const int*   src  = (const int*)d_in[4];
    const int*   dst  = (const int*)d_in[5];
    float* out = (float*)d_out;

    bool   has_rst  = ((size_t)out_size > EHIN);
    float* out_edge = out + (has_rst ? NHF : 0);
    float* rst_dst  = out;

    // NOTE: gemm moved to 4th slot — that's the launch ncu captures.
    k_zero<<<(N_NODES + 255) / 256, 256>>>();
    k_hist<<<(E_EDGES + 255) / 256, 256>>>(dst);
    k_scan1<<<SCAN_BLOCKS, 1024>>>();
    k_gemm<<<(N_NODES + 31) / 32, 256>>>(feat, W);
    k_scan2<<<SCAN_BLOCKS, 1024>>>();
    k_place<<<(E_EDGES + 255) / 256, 256>>>(src, dst);
    k_elr<<<(NH * 32 + 255) / 256, 256>>>(al, ar);
    k_agg<<<N_NODES, 256>>>(feat, rst_dst);
    k_oe<<<N_NODES, 256>>>(out_edge);
    (void)has_rst;
}